// round 4
// baseline (speedup 1.0000x reference)
#include <cuda_runtime.h>
#include <cuda_fp16.h>
#include <cstdint>

// ---------------- problem constants ----------------
#define BATCH   8192
#define KDIM    4096   // input(2048) + hidden(2048)
#define NDIM    2048   // per-gate output
#define TILE_M  256    // CTA rows
#define TILE_N  32     // CTA cols PER GATE (x4 gates)
#define TILE_K  64     // k-tile (128 bytes fp16 per row)
#define NKT     (KDIM / TILE_K)          // 64
#define M_TILES (BATCH / TILE_M)         // 32
#define N_TILES (NDIM / TILE_N)          // 64
#define GRID    (M_TILES * N_TILES)      // 2048
#define NTHREADS 512                     // 16 warps: 8 along M x 2 along N

// smem: per stage: A tile 256x128B = 32KB, W tile (4 gates x 32 rows)x128B = 16KB
#define A_STAGE_BYTES 32768
#define W_STAGE_BYTES 16384
#define STAGE_BYTES   (A_STAGE_BYTES + W_STAGE_BYTES)   // 49152
#define NSTAGES 3
#define SMEM_TOTAL (NSTAGES * STAGE_BYTES)              // 147456

// ---------------- fp16 scratch (device globals: sanctioned scratch path) ---
__device__ __align__(256) __half g_A[(size_t)BATCH * KDIM];     // 67 MB
__device__ __align__(256) __half g_W[(size_t)4 * NDIM * KDIM];  // 67 MB

// ---------------- PTX helpers ----------------
static __device__ __forceinline__ uint32_t smem_u32(const void* p) {
    uint32_t a;
    asm("{ .reg .u64 t; cvta.to.shared.u64 t, %1; cvt.u32.u64 %0, t; }"
        : "=r"(a) : "l"(p));
    return a;
}

static __device__ __forceinline__ void cp_async16(uint32_t saddr, const void* gptr) {
    asm volatile("cp.async.cg.shared.global [%0], [%1], 16;" :: "r"(saddr), "l"(gptr));
}
#define CP_COMMIT() asm volatile("cp.async.commit_group;" ::: "memory")
#define CP_WAIT(n)  asm volatile("cp.async.wait_group %0;" :: "n"(n) : "memory")

#define LDSM_X4(R, addr)                                                     \
    asm volatile("ldmatrix.sync.aligned.m8n8.x4.shared.b16 {%0,%1,%2,%3}, [%4];" \
                 : "=r"((R)[0]), "=r"((R)[1]), "=r"((R)[2]), "=r"((R)[3])    \
                 : "r"(addr))

#define MMA16816(D, A, B0, B1)                                               \
    asm volatile("mma.sync.aligned.m16n8k16.row.col.f32.f16.f16.f32 "        \
                 "{%0,%1,%2,%3}, {%4,%5,%6,%7}, {%8,%9}, {%0,%1,%2,%3};"     \
                 : "+f"((D)[0]), "+f"((D)[1]), "+f"((D)[2]), "+f"((D)[3])    \
                 : "r"((A)[0]), "r"((A)[1]), "r"((A)[2]), "r"((A)[3]),       \
                   "r"(B0), "r"(B1))

// ---------------- activations ----------------
static __device__ __forceinline__ float sigm_f(float x) {
    return __fdividef(1.0f, 1.0f + __expf(-x));
}
static __device__ __forceinline__ float tanh_f(float x) {
    return __fdividef(2.0f, 1.0f + __expf(-2.0f * x)) - 1.0f;
}

// ---------------- pass 1: fp32 -> fp16 conversion ----------------
// g_A[m][k] = k<2048 ? i[m][k] : h[m][k-2048]
// g_W[g*2048 + n][k] = Wg[n][k]
__global__ void __launch_bounds__(256) convert_kernel(
    const float* __restrict__ i_, const float* __restrict__ h_,
    const float* __restrict__ W1, const float* __restrict__ W2,
    const float* __restrict__ W3, const float* __restrict__ W4) {
    const uint32_t NA2 = (uint32_t)((size_t)BATCH * KDIM / 2);  // u32 elems in A
    const uint32_t TOT = NA2 * 2;                                // A + W equal sizes
    uint32_t* Ao = reinterpret_cast<uint32_t*>(g_A);
    uint32_t* Wo = reinterpret_cast<uint32_t*>(g_W);
    uint32_t stride = gridDim.x * blockDim.x;
    for (uint32_t e = blockIdx.x * blockDim.x + threadIdx.x; e < TOT; e += stride) {
        float2 v;
        if (e < NA2) {
            uint32_t m = e >> 11, k2 = e & 2047;
            uint32_t k = k2 * 2;
            if (k < 2048) v = *reinterpret_cast<const float2*>(i_ + (size_t)m * 2048 + k);
            else          v = *reinterpret_cast<const float2*>(h_ + (size_t)m * 2048 + (k - 2048));
            __half2 hh = __floats2half2_rn(v.x, v.y);
            Ao[e] = *reinterpret_cast<uint32_t*>(&hh);
        } else {
            uint32_t e2 = e - NA2;
            uint32_t g = e2 >> 22;                 // 2048*4096/2 = 2^22 u32 per gate
            uint32_t rem = e2 & 0x3FFFFF;
            uint32_t r = rem >> 11, k2 = rem & 2047;
            const float* W = (g == 0) ? W1 : (g == 1) ? W2 : (g == 2) ? W3 : W4;
            v = *reinterpret_cast<const float2*>(W + (size_t)r * KDIM + k2 * 2);
            __half2 hh = __floats2half2_rn(v.x, v.y);
            Wo[e2] = *reinterpret_cast<uint32_t*>(&hh);
        }
    }
}

// ---------------- stage loader: cp.async, 6 x 16B per thread ----------------
// smem chunk (row r, s=0..7) stored at r*128 + ((s ^ (r&7))*16)  (XOR swizzle)
static __device__ __forceinline__ void load_stage(uint32_t stage_base, int m0, int n0,
                                                  int kt, int tid) {
    const __half* Asrc = g_A + (size_t)m0 * KDIM + kt * TILE_K;
    const __half* Wsrc = g_W + (size_t)n0 * KDIM + kt * TILE_K;
#pragma unroll
    for (int i = 0; i < 4; i++) {                 // A: 2048 chunks
        int c = tid + i * NTHREADS;
        int r = c >> 3, s = c & 7;
        uint32_t dst = stage_base + (uint32_t)r * 128 + (uint32_t)((s ^ (r & 7)) << 4);
        cp_async16(dst, Asrc + (size_t)r * KDIM + s * 8);
    }
#pragma unroll
    for (int i = 0; i < 2; i++) {                 // W: 1024 chunks (4 gates x 32 rows)
        int c = tid + i * NTHREADS;
        int wr = c >> 3, s = c & 7;
        int g = wr >> 5, n = wr & 31;
        uint32_t dst = stage_base + A_STAGE_BYTES +
                       (uint32_t)wr * 128 + (uint32_t)((s ^ (wr & 7)) << 4);
        cp_async16(dst, Wsrc + ((size_t)g * NDIM + n) * KDIM + s * 8);
    }
    CP_COMMIT();
}

// ---------------- pass 2: fused 4-gate GEMM + LSTM epilogue ----------------
__global__ void __launch_bounds__(NTHREADS, 1) lstm_gemm_kernel(
    const float* __restrict__ c_,
    const float* __restrict__ b1, const float* __restrict__ b2,
    const float* __restrict__ b3, const float* __restrict__ b4,
    float* __restrict__ hout, float* __restrict__ cout) {
    extern __shared__ char smem[];
    uint32_t sb = smem_u32(smem);
    int tid = threadIdx.x;
    int wid = tid >> 5, lane = tid & 31;
    int wm = wid & 7, wn = wid >> 3;              // 8 warps M x 2 warps N

    // rasterization: 4 groups of 8 m-tiles, n-tile major inside group
    int bid = blockIdx.x;
    int group = bid >> 9, local = bid & 511;      // 512 = 8 mt * 64 nt
    int mt = (group << 3) + (local & 7);
    int nt = local >> 3;
    int m0 = mt * TILE_M, n0 = nt * TILE_N;

    // per-thread smem read offsets (relative to stage base)
    int l7 = lane & 7;
    int hi16 = lane >> 4;                         // A k-chunk select
    int kh = (lane >> 3) & 1;                     // B k-half select
    uint32_t a_row_off[2];
#pragma unroll
    for (int mi = 0; mi < 2; mi++)
        a_row_off[mi] = (uint32_t)(wm * 32 + mi * 16 + (lane & 15)) * 128;
    uint32_t b_row_off[4];
#pragma unroll
    for (int g = 0; g < 4; g++)
        b_row_off[g] = (uint32_t)(g * 32 + wn * 16 + (lane & 7) + ((lane >> 4) << 3)) * 128
                       + A_STAGE_BYTES;

    float acc[4][2][2][4];                        // [gate][mi][ni][frag]
#pragma unroll
    for (int g = 0; g < 4; g++)
#pragma unroll
        for (int mi = 0; mi < 2; mi++)
#pragma unroll
            for (int ni = 0; ni < 2; ni++)
#pragma unroll
                for (int e = 0; e < 4; e++) acc[g][mi][ni][e] = 0.0f;

    load_stage(sb + 0 * STAGE_BYTES, m0, n0, 0, tid);
    load_stage(sb + 1 * STAGE_BYTES, m0, n0, 1, tid);

    for (int kt = 0; kt < NKT; kt++) {
        if (kt + 2 < NKT) load_stage(sb + ((kt + 2) % NSTAGES) * STAGE_BYTES,
                                     m0, n0, kt + 2, tid);
        else CP_COMMIT();                         // keep group arithmetic uniform
        CP_WAIT(2);
        __syncthreads();

        uint32_t stage = sb + (uint32_t)(kt % NSTAGES) * STAGE_BYTES;
#pragma unroll
        for (int ks = 0; ks < 4; ks++) {
            uint32_t a[2][4];
#pragma unroll
            for (int mi = 0; mi < 2; mi++) {
                uint32_t addr = stage + a_row_off[mi] +
                                (uint32_t)((((2 * ks + hi16) ^ l7)) << 4);
                LDSM_X4(a[mi], addr);
            }
            uint32_t b[4][4];
#pragma unroll
            for (int g = 0; g < 4; g++) {
                uint32_t addr = stage + b_row_off[g] +
                                (uint32_t)((((2 * ks + kh) ^ l7)) << 4);
                LDSM_X4(b[g], addr);
            }
#pragma unroll
            for (int g = 0; g < 4; g++)
#pragma unroll
                for (int mi = 0; mi < 2; mi++)
#pragma unroll
                    for (int ni = 0; ni < 2; ni++)
                        MMA16816(acc[g][mi][ni], a[mi], b[g][2 * ni], b[g][2 * ni + 1]);
        }
        __syncthreads();
    }

    // -------- fused LSTM epilogue --------
    int qrow = lane >> 2;
    int qcol = (lane & 3) * 2;
    int colbase = n0 + wn * 16 + qcol;

    float2 bias[4][2];
#pragma unroll
    for (int ni = 0; ni < 2; ni++) {
        bias[0][ni] = *reinterpret_cast<const float2*>(b1 + colbase + ni * 8);
        bias[1][ni] = *reinterpret_cast<const float2*>(b2 + colbase + ni * 8);
        bias[2][ni] = *reinterpret_cast<const float2*>(b3 + colbase + ni * 8);
        bias[3][ni] = *reinterpret_cast<const float2*>(b4 + colbase + ni * 8);
    }

#pragma unroll
    for (int mi = 0; mi < 2; mi++) {
#pragma unroll
        for (int e = 0; e < 2; e++) {             // row half of the m16 tile
            int m = m0 + wm * 32 + mi * 16 + qrow + e * 8;
            const float* crow = c_ + (size_t)m * NDIM;
            float* hrow = hout + (size_t)m * NDIM;
            float* wrow = cout + (size_t)m * NDIM;
#pragma unroll
            for (int ni = 0; ni < 2; ni++) {
                int col = colbase + ni * 8;
                float2 cv = *reinterpret_cast<const float2*>(crow + col);
                float oh[2], oc[2];
#pragma unroll
                for (int p = 0; p < 2; p++) {
                    float bb1 = p ? bias[0][ni].y : bias[0][ni].x;
                    float bb2 = p ? bias[1][ni].y : bias[1][ni].x;
                    float bb3 = p ? bias[2][ni].y : bias[2][ni].x;
                    float bb4 = p ? bias[3][ni].y : bias[3][ni].x;
                    float z1 = acc[0][mi][ni][e * 2 + p] + bb1;
                    float z2 = acc[1][mi][ni][e * 2 + p] + bb2;
                    float z3 = acc[2][mi][ni][e * 2 + p] + bb3;
                    float z4 = acc[3][mi][ni][e * 2 + p] + bb4;
                    float o1 = sigm_f(z1);
                    float o2 = sigm_f(z2);
                    float o3 = tanh_f(z3);
                    float o4 = sigm_f(z4);
                    float cvj = p ? cv.y : cv.x;
                    oc[p] = cvj * o1 + o2 * o3;
                    oh[p] = tanh_f(cvj) * o4;
                }
                *reinterpret_cast<float2*>(hrow + col) = make_float2(oh[0], oh[1]);
                *reinterpret_cast<float2*>(wrow + col) = make_float2(oc[0], oc[1]);
            }
        }
    }
}

// ---------------- launcher ----------------
extern "C" void kernel_launch(void* const* d_in, const int* in_sizes, int n_in,
                              void* d_out, int out_size) {
    const float* i_ = (const float*)d_in[0];
    const float* h_ = (const float*)d_in[1];
    const float* c_ = (const float*)d_in[2];
    const float* W1 = (const float*)d_in[3];
    const float* b1 = (const float*)d_in[4];
    const float* W2 = (const float*)d_in[5];
    const float* b2 = (const float*)d_in[6];
    const float* W3 = (const float*)d_in[7];
    const float* b3 = (const float*)d_in[8];
    const float* W4 = (const float*)d_in[9];
    const float* b4 = (const float*)d_in[10];
    float* out = (float*)d_out;

    cudaFuncSetAttribute(lstm_gemm_kernel,
                         cudaFuncAttributeMaxDynamicSharedMemorySize, SMEM_TOTAL);

    convert_kernel<<<4096, 256>>>(i_, h_, W1, W2, W3, W4);
    lstm_gemm_kernel<<<GRID, NTHREADS, SMEM_TOTAL>>>(
        c_, b1, b2, b3, b4, out, out + (size_t)BATCH * NDIM);
}

// round 6
// speedup vs baseline: 1.1837x; 1.1837x over previous
#include <cuda_runtime.h>
#include <cuda_fp16.h>
#include <cstdint>

// ---------------- problem constants ----------------
#define BATCH   8192
#define KDIM    4096   // input(2048) + hidden(2048)
#define NDIM    2048   // per-gate output
#define TILE_M  128    // CTA rows
#define TILE_N  32     // CTA cols PER GATE (x4 gates)
#define TILE_K  64     // k-tile (128 bytes fp16 per row)
#define NKT     (KDIM / TILE_K)          // 64
#define M_TILES (BATCH / TILE_M)         // 64
#define N_TILES (NDIM / TILE_N)          // 64
#define GRID    (M_TILES * N_TILES)      // 4096
#define NTHREADS 256                     // 8 warps: 4 along M x 2 along N

// smem per stage: A tile 128x128B = 16KB, W tile (4 gates x 32 rows)x128B = 16KB
#define A_STAGE_BYTES 16384
#define W_STAGE_BYTES 16384
#define STAGE_BYTES   (A_STAGE_BYTES + W_STAGE_BYTES)   // 32768
#define NSTAGES 3
#define SMEM_TOTAL (NSTAGES * STAGE_BYTES)              // 98304

// ---------------- fp16 scratch (device globals: sanctioned scratch path) ---
__device__ __align__(256) __half g_A[(size_t)BATCH * KDIM];     // 67 MB
__device__ __align__(256) __half g_W[(size_t)4 * NDIM * KDIM];  // 67 MB

// ---------------- PTX helpers ----------------
static __device__ __forceinline__ uint32_t smem_u32(const void* p) {
    uint32_t a;
    asm("{ .reg .u64 t; cvta.to.shared.u64 t, %1; cvt.u32.u64 %0, t; }"
        : "=r"(a) : "l"(p));
    return a;
}

static __device__ __forceinline__ void cp_async16(uint32_t saddr, const void* gptr) {
    asm volatile("cp.async.cg.shared.global [%0], [%1], 16;" :: "r"(saddr), "l"(gptr));
}
#define CP_COMMIT() asm volatile("cp.async.commit_group;" ::: "memory")
#define CP_WAIT(n)  asm volatile("cp.async.wait_group %0;" :: "n"(n) : "memory")

#define LDSM_X4(R, addr)                                                     \
    asm volatile("ldmatrix.sync.aligned.m8n8.x4.shared.b16 {%0,%1,%2,%3}, [%4];" \
                 : "=r"((R)[0]), "=r"((R)[1]), "=r"((R)[2]), "=r"((R)[3])    \
                 : "r"(addr))

#define MMA16816(D, A, B0, B1)                                               \
    asm volatile("mma.sync.aligned.m16n8k16.row.col.f32.f16.f16.f32 "        \
                 "{%0,%1,%2,%3}, {%4,%5,%6,%7}, {%8,%9}, {%0,%1,%2,%3};"     \
                 : "+f"((D)[0]), "+f"((D)[1]), "+f"((D)[2]), "+f"((D)[3])    \
                 : "r"((A)[0]), "r"((A)[1]), "r"((A)[2]), "r"((A)[3]),       \
                   "r"(B0), "r"(B1))

// ---------------- activations ----------------
static __device__ __forceinline__ float sigm_f(float x) {
    return __fdividef(1.0f, 1.0f + __expf(-x));
}
static __device__ __forceinline__ float tanh_f(float x) {
    return __fdividef(2.0f, 1.0f + __expf(-2.0f * x)) - 1.0f;
}

// ---------------- pass 1: fp32 -> fp16 conversion ----------------
// g_A[m][k] = k<2048 ? i[m][k] : h[m][k-2048]
// g_W[g*2048 + n][k] = Wg[n][k]
__global__ void __launch_bounds__(256) convert_kernel(
    const float* __restrict__ i_, const float* __restrict__ h_,
    const float* __restrict__ W1, const float* __restrict__ W2,
    const float* __restrict__ W3, const float* __restrict__ W4) {
    const uint32_t NA2 = (uint32_t)((size_t)BATCH * KDIM / 2);  // u32 elems in A
    const uint32_t TOT = NA2 * 2;                                // A + W equal sizes
    uint32_t* Ao = reinterpret_cast<uint32_t*>(g_A);
    uint32_t* Wo = reinterpret_cast<uint32_t*>(g_W);
    uint32_t stride = gridDim.x * blockDim.x;
    for (uint32_t e = blockIdx.x * blockDim.x + threadIdx.x; e < TOT; e += stride) {
        float2 v;
        if (e < NA2) {
            uint32_t m = e >> 11, k2 = e & 2047;
            uint32_t k = k2 * 2;
            if (k < 2048) v = *reinterpret_cast<const float2*>(i_ + (size_t)m * 2048 + k);
            else          v = *reinterpret_cast<const float2*>(h_ + (size_t)m * 2048 + (k - 2048));
            __half2 hh = __floats2half2_rn(v.x, v.y);
            Ao[e] = *reinterpret_cast<uint32_t*>(&hh);
        } else {
            uint32_t e2 = e - NA2;
            uint32_t g = e2 >> 22;                 // 2048*4096/2 = 2^22 u32 per gate
            uint32_t rem = e2 & 0x3FFFFF;
            uint32_t r = rem >> 11, k2 = rem & 2047;
            const float* W = (g == 0) ? W1 : (g == 1) ? W2 : (g == 2) ? W3 : W4;
            v = *reinterpret_cast<const float2*>(W + (size_t)r * KDIM + k2 * 2);
            __half2 hh = __floats2half2_rn(v.x, v.y);
            Wo[e2] = *reinterpret_cast<uint32_t*>(&hh);
        }
    }
}

// ---------------- stage loader: cp.async, 8 x 16B per thread ----------------
// smem chunk (row r, s=0..7) stored at r*128 + ((s ^ (r&7))*16)  (XOR swizzle)
static __device__ __forceinline__ void load_stage(uint32_t stage_base, int m0, int n0,
                                                  int kt, int tid) {
    const __half* Asrc = g_A + (size_t)m0 * KDIM + kt * TILE_K;
    const __half* Wsrc = g_W + (size_t)n0 * KDIM + kt * TILE_K;
#pragma unroll
    for (int i = 0; i < 4; i++) {                 // A: 1024 chunks (128 rows x 8)
        int c = tid + i * NTHREADS;
        int r = c >> 3, s = c & 7;
        uint32_t dst = stage_base + (uint32_t)r * 128 + (uint32_t)((s ^ (r & 7)) << 4);
        cp_async16(dst, Asrc + (size_t)r * KDIM + s * 8);
    }
#pragma unroll
    for (int i = 0; i < 4; i++) {                 // W: 1024 chunks (4 gates x 32 rows)
        int c = tid + i * NTHREADS;
        int wr = c >> 3, s = c & 7;
        int g = wr >> 5, n = wr & 31;
        uint32_t dst = stage_base + A_STAGE_BYTES +
                       (uint32_t)wr * 128 + (uint32_t)((s ^ (wr & 7)) << 4);
        cp_async16(dst, Wsrc + ((size_t)g * NDIM + n) * KDIM + s * 8);
    }
    CP_COMMIT();
}

// ---------------- pass 2: fused 4-gate GEMM + LSTM epilogue ----------------
// 2 CTAs / SM: per-CTA barriers stagger so one CTA's HMMA covers the other's sync.
__global__ void __launch_bounds__(NTHREADS, 2) lstm_gemm_kernel(
    const float* __restrict__ c_,
    const float* __restrict__ b1, const float* __restrict__ b2,
    const float* __restrict__ b3, const float* __restrict__ b4,
    float* __restrict__ hout, float* __restrict__ cout) {
    extern __shared__ char smem[];
    uint32_t sb = smem_u32(smem);
    int tid = threadIdx.x;
    int wid = tid >> 5, lane = tid & 31;
    int wm = wid & 3, wn = wid >> 2;              // 4 warps M x 2 warps N

    // rasterization: 8 groups of 8 m-tiles, m fastest inside group
    int bid = blockIdx.x;
    int group = bid >> 9, local = bid & 511;      // 512 = 8 mt * 64 nt
    int mt = (group << 3) + (local & 7);
    int nt = local >> 3;
    int m0 = mt * TILE_M, n0 = nt * TILE_N;

    // per-thread smem read offsets (relative to stage base)
    int l7 = lane & 7;
    int hi16 = lane >> 4;                         // A k-chunk select
    int kh = (lane >> 3) & 1;                     // B k-half select
    uint32_t a_row_off[2];
#pragma unroll
    for (int mi = 0; mi < 2; mi++)
        a_row_off[mi] = (uint32_t)(wm * 32 + mi * 16 + (lane & 15)) * 128;
    uint32_t b_row_off[4];
#pragma unroll
    for (int g = 0; g < 4; g++)
        b_row_off[g] = (uint32_t)(g * 32 + wn * 16 + (lane & 7) + ((lane >> 4) << 3)) * 128
                       + A_STAGE_BYTES;

    float acc[4][2][2][4];                        // [gate][mi][ni][frag]
#pragma unroll
    for (int g = 0; g < 4; g++)
#pragma unroll
        for (int mi = 0; mi < 2; mi++)
#pragma unroll
            for (int ni = 0; ni < 2; ni++)
#pragma unroll
                for (int e = 0; e < 4; e++) acc[g][mi][ni][e] = 0.0f;

    load_stage(sb + 0 * STAGE_BYTES, m0, n0, 0, tid);
    load_stage(sb + 1 * STAGE_BYTES, m0, n0, 1, tid);

    for (int kt = 0; kt < NKT; kt++) {
        // group for tile kt is second-newest here -> wait_group(1) completes it
        CP_WAIT(1);
        __syncthreads();   // also proves all reads of stage kt-1 are done
        // stage (kt+2)%3 == (kt-1)%3: safe to overwrite only AFTER the barrier
        if (kt + 2 < NKT) load_stage(sb + ((kt + 2) % NSTAGES) * STAGE_BYTES,
                                     m0, n0, kt + 2, tid);
        else CP_COMMIT();                         // keep group arithmetic uniform

        uint32_t stage = sb + (uint32_t)(kt % NSTAGES) * STAGE_BYTES;
#pragma unroll
        for (int ks = 0; ks < 4; ks++) {
            uint32_t a[2][4];
#pragma unroll
            for (int mi = 0; mi < 2; mi++) {
                uint32_t addr = stage + a_row_off[mi] +
                                (uint32_t)((((2 * ks + hi16) ^ l7)) << 4);
                LDSM_X4(a[mi], addr);
            }
            uint32_t b[4][4];
#pragma unroll
            for (int g = 0; g < 4; g++) {
                uint32_t addr = stage + b_row_off[g] +
                                (uint32_t)((((2 * ks + kh) ^ l7)) << 4);
                LDSM_X4(b[g], addr);
            }
#pragma unroll
            for (int g = 0; g < 4; g++)
#pragma unroll
                for (int mi = 0; mi < 2; mi++)
#pragma unroll
                    for (int ni = 0; ni < 2; ni++)
                        MMA16816(acc[g][mi][ni], a[mi], b[g][2 * ni], b[g][2 * ni + 1]);
        }
    }

    // -------- fused LSTM epilogue --------
    int qrow = lane >> 2;
    int qcol = (lane & 3) * 2;
    int colbase = n0 + wn * 16 + qcol;

    float2 bias[4][2];
#pragma unroll
    for (int ni = 0; ni < 2; ni++) {
        bias[0][ni] = *reinterpret_cast<const float2*>(b1 + colbase + ni * 8);
        bias[1][ni] = *reinterpret_cast<const float2*>(b2 + colbase + ni * 8);
        bias[2][ni] = *reinterpret_cast<const float2*>(b3 + colbase + ni * 8);
        bias[3][ni] = *reinterpret_cast<const float2*>(b4 + colbase + ni * 8);
    }

#pragma unroll
    for (int mi = 0; mi < 2; mi++) {
#pragma unroll
        for (int e = 0; e < 2; e++) {             // row half of the m16 tile
            int m = m0 + wm * 32 + mi * 16 + qrow + e * 8;
            const float* crow = c_ + (size_t)m * NDIM;
            float* hrow = hout + (size_t)m * NDIM;
            float* wrow = cout + (size_t)m * NDIM;
#pragma unroll
            for (int ni = 0; ni < 2; ni++) {
                int col = colbase + ni * 8;
                float2 cv = *reinterpret_cast<const float2*>(crow + col);
                float oh[2], oc[2];
#pragma unroll
                for (int p = 0; p < 2; p++) {
                    float bb1 = p ? bias[0][ni].y : bias[0][ni].x;
                    float bb2 = p ? bias[1][ni].y : bias[1][ni].x;
                    float bb3 = p ? bias[2][ni].y : bias[2][ni].x;
                    float bb4 = p ? bias[3][ni].y : bias[3][ni].x;
                    float z1 = acc[0][mi][ni][e * 2 + p] + bb1;
                    float z2 = acc[1][mi][ni][e * 2 + p] + bb2;
                    float z3 = acc[2][mi][ni][e * 2 + p] + bb3;
                    float z4 = acc[3][mi][ni][e * 2 + p] + bb4;
                    float o1 = sigm_f(z1);
                    float o2 = sigm_f(z2);
                    float o3 = tanh_f(z3);
                    float o4 = sigm_f(z4);
                    float cvj = p ? cv.y : cv.x;
                    oc[p] = cvj * o1 + o2 * o3;
                    oh[p] = tanh_f(cvj) * o4;
                }
                *reinterpret_cast<float2*>(hrow + col) = make_float2(oh[0], oh[1]);
                *reinterpret_cast<float2*>(wrow + col) = make_float2(oc[0], oc[1]);
            }
        }
    }
}

// ---------------- launcher ----------------
extern "C" void kernel_launch(void* const* d_in, const int* in_sizes, int n_in,
                              void* d_out, int out_size) {
    const float* i_ = (const float*)d_in[0];
    const float* h_ = (const float*)d_in[1];
    const float* c_ = (const float*)d_in[2];
    const float* W1 = (const float*)d_in[3];
    const float* b1 = (const float*)d_in[4];
    const float* W2 = (const float*)d_in[5];
    const float* b2 = (const float*)d_in[6];
    const float* W3 = (const float*)d_in[7];
    const float* b3 = (const float*)d_in[8];
    const float* W4 = (const float*)d_in[9];
    const float* b4 = (const float*)d_in[10];
    float* out = (float*)d_out;

    cudaFuncSetAttribute(lstm_gemm_kernel,
                         cudaFuncAttributeMaxDynamicSharedMemorySize, SMEM_TOTAL);

    convert_kernel<<<4096, 256>>>(i_, h_, W1, W2, W3, W4);
    lstm_gemm_kernel<<<GRID, NTHREADS, SMEM_TOTAL>>>(
        c_, b1, b2, b3, b4, out, out + (size_t)BATCH * NDIM);
}